// round 7
// baseline (speedup 1.0000x reference)
#include <cuda_runtime.h>
#include <cuda_bf16.h>
#include <cstdint>

#define N_NODES 100000
#define N_EDGES 1600000
#define HID     128
#define IN_NODE 64
#define IN_EDGE 16
#define NEG_SLOPE 0.01f
#define LN_EPS    1e-5f

// Persistent scratch (no allocations allowed). float4 for 16B alignment.
__device__ float4 g_H  [(size_t)N_NODES * (HID / 4)];
__device__ float4 g_H0 [(size_t)N_NODES * (HID / 4)];
__device__ float4 g_AGG[(size_t)N_NODES * (HID / 4)];

// Edge indices normalized to int32 regardless of input dtype.
__device__ int g_src[N_EDGES];
__device__ int g_dst[N_EDGES];
__device__ int g_is32;   // 1 if edge_index buffer is int32, 0 if int64

// ---------------------------------------------------------------------------
// Detect edge_index dtype by sampling odd 32-bit words.
// int64 (nonneg, < 2^31): odd words are high-words == 0 -> OR == 0.
// int32: odd words are random indices in [0, N_NODES) -> OR != 0 (w.p. ~1).
// ---------------------------------------------------------------------------
__global__ void detect_kernel(const int* __restrict__ ei32)
{
    __shared__ int s_or;
    if (threadIdx.x == 0) s_or = 0;
    __syncthreads();
    int v = 0;
    for (int i = threadIdx.x; i < 4096; i += blockDim.x)
        v |= ei32[2 * i + 1];
    atomicOr(&s_or, v);
    __syncthreads();
    if (threadIdx.x == 0) g_is32 = (s_or != 0) ? 1 : 0;
}

// Normalize edge_index into g_src / g_dst (int32).
__global__ void convert_kernel(const int* __restrict__ ei32)
{
    int i = blockIdx.x * blockDim.x + threadIdx.x;
    if (i >= 2 * N_EDGES) return;
    // int32 layout: element i at word i. int64 layout: low word of element i at 2*i.
    int v = g_is32 ? ei32[i] : ei32[2 * i];
    if (i < N_EDGES) g_src[i] = v;
    else             g_dst[i - N_EDGES] = v;
}

// ---------------------------------------------------------------------------
// Node linear: h = X @ W_node + b_node   (X: [N,64], W: [64,128])
// Writes g_H, g_H0 and g_AGG (agg seeded with h so atomics produce h + sum).
// Block = (32,8): thread (tx,ty) computes rows row0+ty*4..+3, cols tx*4..+3.
// ---------------------------------------------------------------------------
__global__ void __launch_bounds__(256) node_linear_kernel(
    const float* __restrict__ X,
    const float* __restrict__ W,
    const float* __restrict__ B)
{
    __shared__ float As[32][IN_NODE];   // 8 KB
    __shared__ float Ws[32][HID];       // 16 KB
    const int tx = threadIdx.x, ty = threadIdx.y;
    const int tid = ty * 32 + tx;
    const int row0 = blockIdx.x * 32;

    const float4* X4 = (const float4*)X;
    for (int i = tid; i < 32 * 16; i += 256) {
        int r = i >> 4, c = i & 15;
        ((float4*)&As[r][0])[c] = X4[(size_t)(row0 + r) * 16 + c];
    }

    float4 acc[4];
#pragma unroll
    for (int r = 0; r < 4; r++) acc[r] = make_float4(0.f, 0.f, 0.f, 0.f);

    const float4* W4 = (const float4*)W;
    for (int kk = 0; kk < IN_NODE; kk += 32) {
        __syncthreads();
        for (int i = tid; i < 32 * 32; i += 256) {
            int r = i >> 5, c = i & 31;
            ((float4*)&Ws[r][0])[c] = W4[(size_t)(kk + r) * 32 + c];
        }
        __syncthreads();
#pragma unroll
        for (int k = 0; k < 32; k += 4) {
            float4 w0 = *(const float4*)&Ws[k + 0][tx * 4];
            float4 w1 = *(const float4*)&Ws[k + 1][tx * 4];
            float4 w2 = *(const float4*)&Ws[k + 2][tx * 4];
            float4 w3 = *(const float4*)&Ws[k + 3][tx * 4];
#pragma unroll
            for (int r = 0; r < 4; r++) {
                float4 a = *(const float4*)&As[ty * 4 + r][kk + k];
                acc[r].x = fmaf(a.x, w0.x, acc[r].x);
                acc[r].y = fmaf(a.x, w0.y, acc[r].y);
                acc[r].z = fmaf(a.x, w0.z, acc[r].z);
                acc[r].w = fmaf(a.x, w0.w, acc[r].w);
                acc[r].x = fmaf(a.y, w1.x, acc[r].x);
                acc[r].y = fmaf(a.y, w1.y, acc[r].y);
                acc[r].z = fmaf(a.y, w1.z, acc[r].z);
                acc[r].w = fmaf(a.y, w1.w, acc[r].w);
                acc[r].x = fmaf(a.z, w2.x, acc[r].x);
                acc[r].y = fmaf(a.z, w2.y, acc[r].y);
                acc[r].z = fmaf(a.z, w2.z, acc[r].z);
                acc[r].w = fmaf(a.z, w2.w, acc[r].w);
                acc[r].x = fmaf(a.w, w3.x, acc[r].x);
                acc[r].y = fmaf(a.w, w3.y, acc[r].y);
                acc[r].z = fmaf(a.w, w3.z, acc[r].z);
                acc[r].w = fmaf(a.w, w3.w, acc[r].w);
            }
        }
    }

    float4 b4 = ((const float4*)B)[tx];
#pragma unroll
    for (int r = 0; r < 4; r++) {
        int grow = row0 + ty * 4 + r;
        float4 o = make_float4(acc[r].x + b4.x, acc[r].y + b4.y,
                               acc[r].z + b4.z, acc[r].w + b4.w);
        size_t off = (size_t)grow * 32 + tx;
        g_H[off]   = o;
        g_H0[off]  = o;
        g_AGG[off] = o;
    }
}

// ---------------------------------------------------------------------------
// Message kernel (per layer): for each edge (s,d):
//   e = edge_attr @ W_edge + b_edge   (recomputed, W_edge column in registers)
//   msg = relu(h[s] + e);  AGG[d] += msg  (red.global.add.v4.f32)
// One warp per edge; lane owns cols lane*4..+3.
// ---------------------------------------------------------------------------
__global__ void __launch_bounds__(256) message_kernel(
    const float* __restrict__ EA,
    const float* __restrict__ WE,
    const float* __restrict__ BE)
{
    const int lane = threadIdx.x & 31;
    const int warp  = (blockIdx.x * blockDim.x + threadIdx.x) >> 5;
    const int nwarp = (gridDim.x * blockDim.x) >> 5;

    const float4* WE4 = (const float4*)WE;
    float4 wreg[16];
#pragma unroll
    for (int k = 0; k < 16; k++) wreg[k] = WE4[k * 32 + lane];
    const float4 be = ((const float4*)BE)[lane];

    const float4* EA4 = (const float4*)EA;

    for (int e = warp; e < N_EDGES; e += nwarp) {
        int s = g_src[e];
        int d = g_dst[e];
        if ((unsigned)s >= N_NODES || (unsigned)d >= N_NODES) continue;
        float4 ea0 = __ldg(&EA4[(size_t)e * 4 + 0]);
        float4 ea1 = __ldg(&EA4[(size_t)e * 4 + 1]);
        float4 ea2 = __ldg(&EA4[(size_t)e * 4 + 2]);
        float4 ea3 = __ldg(&EA4[(size_t)e * 4 + 3]);
        float ev[16] = { ea0.x, ea0.y, ea0.z, ea0.w,
                         ea1.x, ea1.y, ea1.z, ea1.w,
                         ea2.x, ea2.y, ea2.z, ea2.w,
                         ea3.x, ea3.y, ea3.z, ea3.w };
        float4 acc = be;
#pragma unroll
        for (int k = 0; k < 16; k++) {
            acc.x = fmaf(ev[k], wreg[k].x, acc.x);
            acc.y = fmaf(ev[k], wreg[k].y, acc.y);
            acc.z = fmaf(ev[k], wreg[k].z, acc.z);
            acc.w = fmaf(ev[k], wreg[k].w, acc.w);
        }
        float4 hv = g_H[(size_t)s * 32 + lane];
        float mx = fmaxf(hv.x + acc.x, 0.f);
        float my = fmaxf(hv.y + acc.y, 0.f);
        float mz = fmaxf(hv.z + acc.z, 0.f);
        float mw = fmaxf(hv.w + acc.w, 0.f);
        float4* p = &g_AGG[(size_t)d * 32 + lane];
        asm volatile("red.global.add.v4.f32 [%0], {%1,%2,%3,%4};"
                     :: "l"(p), "f"(mx), "f"(my), "f"(mz), "f"(mw)
                     : "memory");
    }
}

// ---------------------------------------------------------------------------
// Conv GEMM: H = leaky_relu(AGG @ W + b); also re-seed AGG := H for next layer.
// ---------------------------------------------------------------------------
__global__ void __launch_bounds__(256) conv_kernel(
    const float* __restrict__ W,
    const float* __restrict__ B)
{
    __shared__ float As[32][HID];   // 16 KB
    __shared__ float Ws[32][HID];   // 16 KB
    const int tx = threadIdx.x, ty = threadIdx.y;
    const int tid = ty * 32 + tx;
    const int row0 = blockIdx.x * 32;

    for (int i = tid; i < 32 * 32; i += 256) {
        int r = i >> 5, c = i & 31;
        ((float4*)&As[r][0])[c] = g_AGG[(size_t)(row0 + r) * 32 + c];
    }

    float4 acc[4];
#pragma unroll
    for (int r = 0; r < 4; r++) acc[r] = make_float4(0.f, 0.f, 0.f, 0.f);

    const float4* W4 = (const float4*)W;
    for (int kk = 0; kk < HID; kk += 32) {
        __syncthreads();
        for (int i = tid; i < 32 * 32; i += 256) {
            int r = i >> 5, c = i & 31;
            ((float4*)&Ws[r][0])[c] = W4[(size_t)(kk + r) * 32 + c];
        }
        __syncthreads();
#pragma unroll
        for (int k = 0; k < 32; k += 4) {
            float4 w0 = *(const float4*)&Ws[k + 0][tx * 4];
            float4 w1 = *(const float4*)&Ws[k + 1][tx * 4];
            float4 w2 = *(const float4*)&Ws[k + 2][tx * 4];
            float4 w3 = *(const float4*)&Ws[k + 3][tx * 4];
#pragma unroll
            for (int r = 0; r < 4; r++) {
                float4 a = *(const float4*)&As[ty * 4 + r][kk + k];
                acc[r].x = fmaf(a.x, w0.x, acc[r].x);
                acc[r].y = fmaf(a.x, w0.y, acc[r].y);
                acc[r].z = fmaf(a.x, w0.z, acc[r].z);
                acc[r].w = fmaf(a.x, w0.w, acc[r].w);
                acc[r].x = fmaf(a.y, w1.x, acc[r].x);
                acc[r].y = fmaf(a.y, w1.y, acc[r].y);
                acc[r].z = fmaf(a.y, w1.z, acc[r].z);
                acc[r].w = fmaf(a.y, w1.w, acc[r].w);
                acc[r].x = fmaf(a.z, w2.x, acc[r].x);
                acc[r].y = fmaf(a.z, w2.y, acc[r].y);
                acc[r].z = fmaf(a.z, w2.z, acc[r].z);
                acc[r].w = fmaf(a.z, w2.w, acc[r].w);
                acc[r].x = fmaf(a.w, w3.x, acc[r].x);
                acc[r].y = fmaf(a.w, w3.y, acc[r].y);
                acc[r].z = fmaf(a.w, w3.z, acc[r].z);
                acc[r].w = fmaf(a.w, w3.w, acc[r].w);
            }
        }
    }

    float4 b4 = ((const float4*)B)[tx];
#pragma unroll
    for (int r = 0; r < 4; r++) {
        int grow = row0 + ty * 4 + r;
        float ox = acc[r].x + b4.x;
        float oy = acc[r].y + b4.y;
        float oz = acc[r].z + b4.z;
        float ow = acc[r].w + b4.w;
        ox = (ox >= 0.f) ? ox : NEG_SLOPE * ox;
        oy = (oy >= 0.f) ? oy : NEG_SLOPE * oy;
        oz = (oz >= 0.f) ? oz : NEG_SLOPE * oz;
        ow = (ow >= 0.f) ? ow : NEG_SLOPE * ow;
        float4 o = make_float4(ox, oy, oz, ow);
        size_t off = (size_t)grow * 32 + tx;
        g_H[off]   = o;
        g_AGG[off] = o;   // seed next layer's aggregation with h
    }
}

// ---------------------------------------------------------------------------
// Head: y = (H0 + H) @ W_head + b; out = LayerNorm(y)*gamma + beta
// Each warp (fixed ty) owns 4 full rows -> LN via warp allreduce.
// ---------------------------------------------------------------------------
__global__ void __launch_bounds__(256) head_kernel(
    const float* __restrict__ W,
    const float* __restrict__ B,
    const float* __restrict__ G,
    const float* __restrict__ BT,
    float* __restrict__ OUT)
{
    __shared__ float As[32][HID];
    __shared__ float Ws[32][HID];
    const int tx = threadIdx.x, ty = threadIdx.y;
    const int tid = ty * 32 + tx;
    const int row0 = blockIdx.x * 32;

    for (int i = tid; i < 32 * 32; i += 256) {
        int r = i >> 5, c = i & 31;
        size_t off = (size_t)(row0 + r) * 32 + c;
        float4 a = g_H0[off];
        float4 b = g_H[off];
        ((float4*)&As[r][0])[c] =
            make_float4(a.x + b.x, a.y + b.y, a.z + b.z, a.w + b.w);
    }

    float4 acc[4];
#pragma unroll
    for (int r = 0; r < 4; r++) acc[r] = make_float4(0.f, 0.f, 0.f, 0.f);

    const float4* W4 = (const float4*)W;
    for (int kk = 0; kk < HID; kk += 32) {
        __syncthreads();
        for (int i = tid; i < 32 * 32; i += 256) {
            int r = i >> 5, c = i & 31;
            ((float4*)&Ws[r][0])[c] = W4[(size_t)(kk + r) * 32 + c];
        }
        __syncthreads();
#pragma unroll
        for (int k = 0; k < 32; k += 4) {
            float4 w0 = *(const float4*)&Ws[k + 0][tx * 4];
            float4 w1 = *(const float4*)&Ws[k + 1][tx * 4];
            float4 w2 = *(const float4*)&Ws[k + 2][tx * 4];
            float4 w3 = *(const float4*)&Ws[k + 3][tx * 4];
#pragma unroll
            for (int r = 0; r < 4; r++) {
                float4 a = *(const float4*)&As[ty * 4 + r][kk + k];
                acc[r].x = fmaf(a.x, w0.x, acc[r].x);
                acc[r].y = fmaf(a.x, w0.y, acc[r].y);
                acc[r].z = fmaf(a.x, w0.z, acc[r].z);
                acc[r].w = fmaf(a.x, w0.w, acc[r].w);
                acc[r].x = fmaf(a.y, w1.x, acc[r].x);
                acc[r].y = fmaf(a.y, w1.y, acc[r].y);
                acc[r].z = fmaf(a.y, w1.z, acc[r].z);
                acc[r].w = fmaf(a.y, w1.w, acc[r].w);
                acc[r].x = fmaf(a.z, w2.x, acc[r].x);
                acc[r].y = fmaf(a.z, w2.y, acc[r].y);
                acc[r].z = fmaf(a.z, w2.z, acc[r].z);
                acc[r].w = fmaf(a.z, w2.w, acc[r].w);
                acc[r].x = fmaf(a.w, w3.x, acc[r].x);
                acc[r].y = fmaf(a.w, w3.y, acc[r].y);
                acc[r].z = fmaf(a.w, w3.z, acc[r].z);
                acc[r].w = fmaf(a.w, w3.w, acc[r].w);
            }
        }
    }

    float4 b4 = ((const float4*)B)[tx];
    float4 g4 = ((const float4*)G)[tx];
    float4 t4 = ((const float4*)BT)[tx];
    float4* OUT4 = (float4*)OUT;

#pragma unroll
    for (int r = 0; r < 4; r++) {
        int grow = row0 + ty * 4 + r;
        float yx = acc[r].x + b4.x;
        float yy = acc[r].y + b4.y;
        float yz = acc[r].z + b4.z;
        float yw = acc[r].w + b4.w;
        float s = yx + yy + yz + yw;
#pragma unroll
        for (int off = 16; off > 0; off >>= 1)
            s += __shfl_xor_sync(0xffffffffu, s, off);
        float mu = s * (1.0f / HID);
        float dx = yx - mu, dy = yy - mu, dz = yz - mu, dw = yw - mu;
        float q = dx * dx + dy * dy + dz * dz + dw * dw;
#pragma unroll
        for (int off = 16; off > 0; off >>= 1)
            q += __shfl_xor_sync(0xffffffffu, q, off);
        float inv = rsqrtf(q * (1.0f / HID) + LN_EPS);
        float4 o = make_float4(dx * inv * g4.x + t4.x,
                               dy * inv * g4.y + t4.y,
                               dz * inv * g4.z + t4.z,
                               dw * inv * g4.w + t4.w);
        OUT4[(size_t)grow * 32 + tx] = o;
    }
}

// ---------------------------------------------------------------------------
extern "C" void kernel_launch(void* const* d_in, const int* in_sizes, int n_in,
                              void* d_out, int out_size)
{
    const float* x   = (const float*)d_in[0];
    const float* ea  = (const float*)d_in[1];
    const int*   ei  = (const int*)d_in[2];     // dtype resolved on device
    const float* Wn  = (const float*)d_in[3];
    const float* bn  = (const float*)d_in[4];
    const float* We  = (const float*)d_in[5];
    const float* be  = (const float*)d_in[6];
    const float* Wc  = (const float*)d_in[7];
    const float* bc  = (const float*)d_in[8];
    const float* Wh  = (const float*)d_in[9];
    const float* bh  = (const float*)d_in[10];
    const float* gam = (const float*)d_in[11];
    const float* bet = (const float*)d_in[12];
    float* out = (float*)d_out;

    dim3 blk(32, 8);
    const int gemm_grid = N_NODES / 32;   // 3125 (exact)

    detect_kernel<<<1, 256>>>(ei);
    convert_kernel<<<(2 * N_EDGES + 255) / 256, 256>>>(ei);

    node_linear_kernel<<<gemm_grid, blk>>>(x, Wn, bn);
    for (int l = 0; l < 3; l++) {
        message_kernel<<<2048, 256>>>(ea, We, be);
        conv_kernel<<<gemm_grid, blk>>>(Wc + (size_t)l * HID * HID, bc + l * HID);
    }
    head_kernel<<<gemm_grid, blk>>>(Wh, bh, gam, bet, out);
}

// round 8
// speedup vs baseline: 1.6340x; 1.6340x over previous
#include <cuda_runtime.h>
#include <cuda_bf16.h>
#include <cstdint>

#define N_NODES 100000
#define N_EDGES 1600000
#define HID     128
#define IN_NODE 64
#define IN_EDGE 16
#define NEG_SLOPE 0.01f
#define LN_EPS    1e-5f

// Persistent scratch (no allocations allowed). float4 for 16B alignment.
__device__ float4 g_H  [(size_t)N_NODES * (HID / 4)];   // 51.2 MB
__device__ float4 g_H0 [(size_t)N_NODES * (HID / 4)];   // 51.2 MB
__device__ float4 g_AGG[(size_t)N_NODES * (HID / 4)];   // 51.2 MB
__device__ float4 g_E  [(size_t)N_EDGES * (HID / 4)];   // 819.2 MB: e = ea@We + be

// Edge indices normalized to int32 regardless of input dtype.
__device__ int g_src[N_EDGES];
__device__ int g_dst[N_EDGES];
__device__ int g_is32;   // 1 if edge_index buffer is int32, 0 if int64

// ---------------------------------------------------------------------------
// Detect edge_index dtype by sampling odd 32-bit words.
// int64 (nonneg, < 2^31): odd words are high-words == 0 -> OR == 0.
// int32: odd words are random indices in [0, N_NODES) -> OR != 0 (w.p. ~1).
// ---------------------------------------------------------------------------
__global__ void detect_kernel(const int* __restrict__ ei32)
{
    __shared__ int s_or;
    if (threadIdx.x == 0) s_or = 0;
    __syncthreads();
    int v = 0;
    for (int i = threadIdx.x; i < 4096; i += blockDim.x)
        v |= ei32[2 * i + 1];
    atomicOr(&s_or, v);
    __syncthreads();
    if (threadIdx.x == 0) g_is32 = (s_or != 0) ? 1 : 0;
}

// Normalize edge_index into g_src / g_dst (int32).
__global__ void convert_kernel(const int* __restrict__ ei32)
{
    int i = blockIdx.x * blockDim.x + threadIdx.x;
    if (i >= 2 * N_EDGES) return;
    int v = g_is32 ? ei32[i] : ei32[2 * i];
    if (i < N_EDGES) g_src[i] = v;
    else             g_dst[i - N_EDGES] = v;
}

// ---------------------------------------------------------------------------
// Edge linear (once per launch): g_E[e] = edge_attr[e] @ W_edge + b_edge.
// One warp per edge (grid-stride); lane owns cols lane*4..+3.
// W_edge column quad in registers (64 regs — fine, runs once, fma-bound).
// ---------------------------------------------------------------------------
__global__ void __launch_bounds__(256) edge_linear_kernel(
    const float* __restrict__ EA,
    const float* __restrict__ WE,
    const float* __restrict__ BE)
{
    const int lane = threadIdx.x & 31;
    const int warp  = (blockIdx.x * blockDim.x + threadIdx.x) >> 5;
    const int nwarp = (gridDim.x * blockDim.x) >> 5;

    const float4* WE4 = (const float4*)WE;
    float4 wreg[16];
#pragma unroll
    for (int k = 0; k < 16; k++) wreg[k] = WE4[k * 32 + lane];
    const float4 be = ((const float4*)BE)[lane];

    const float4* EA4 = (const float4*)EA;

    for (int e = warp; e < N_EDGES; e += nwarp) {
        float4 ea0 = __ldg(&EA4[(size_t)e * 4 + 0]);
        float4 ea1 = __ldg(&EA4[(size_t)e * 4 + 1]);
        float4 ea2 = __ldg(&EA4[(size_t)e * 4 + 2]);
        float4 ea3 = __ldg(&EA4[(size_t)e * 4 + 3]);
        float ev[16] = { ea0.x, ea0.y, ea0.z, ea0.w,
                         ea1.x, ea1.y, ea1.z, ea1.w,
                         ea2.x, ea2.y, ea2.z, ea2.w,
                         ea3.x, ea3.y, ea3.z, ea3.w };
        float4 acc = be;
#pragma unroll
        for (int k = 0; k < 16; k++) {
            acc.x = fmaf(ev[k], wreg[k].x, acc.x);
            acc.y = fmaf(ev[k], wreg[k].y, acc.y);
            acc.z = fmaf(ev[k], wreg[k].z, acc.z);
            acc.w = fmaf(ev[k], wreg[k].w, acc.w);
        }
        g_E[(size_t)e * 32 + lane] = acc;
    }
}

// ---------------------------------------------------------------------------
// Message kernel (per layer): AGG[d] += relu(h[s] + e)  via red.global.add.v4.
// Pure streaming: ~30 regs -> full occupancy. 2 edges per warp, no loop.
// ---------------------------------------------------------------------------
__global__ void __launch_bounds__(256) message_kernel()
{
    const int lane = threadIdx.x & 31;
    const int warp = (blockIdx.x * blockDim.x + threadIdx.x) >> 5;
    const int e0 = warp * 2;
    if (e0 >= N_EDGES) return;
    const int e1 = e0 + 1;

    int s0 = g_src[e0], d0 = g_dst[e0];
    int s1 = g_src[e1], d1 = g_dst[e1];

    float4 ev0 = g_E[(size_t)e0 * 32 + lane];
    float4 ev1 = g_E[(size_t)e1 * 32 + lane];

    bool ok0 = (unsigned)s0 < N_NODES && (unsigned)d0 < N_NODES;
    bool ok1 = (unsigned)s1 < N_NODES && (unsigned)d1 < N_NODES;

    float4 h0 = ok0 ? g_H[(size_t)s0 * 32 + lane] : make_float4(0,0,0,0);
    float4 h1 = ok1 ? g_H[(size_t)s1 * 32 + lane] : make_float4(0,0,0,0);

    if (ok0) {
        float mx = fmaxf(h0.x + ev0.x, 0.f);
        float my = fmaxf(h0.y + ev0.y, 0.f);
        float mz = fmaxf(h0.z + ev0.z, 0.f);
        float mw = fmaxf(h0.w + ev0.w, 0.f);
        float4* p = &g_AGG[(size_t)d0 * 32 + lane];
        asm volatile("red.global.add.v4.f32 [%0], {%1,%2,%3,%4};"
                     :: "l"(p), "f"(mx), "f"(my), "f"(mz), "f"(mw) : "memory");
    }
    if (ok1) {
        float mx = fmaxf(h1.x + ev1.x, 0.f);
        float my = fmaxf(h1.y + ev1.y, 0.f);
        float mz = fmaxf(h1.z + ev1.z, 0.f);
        float mw = fmaxf(h1.w + ev1.w, 0.f);
        float4* p = &g_AGG[(size_t)d1 * 32 + lane];
        asm volatile("red.global.add.v4.f32 [%0], {%1,%2,%3,%4};"
                     :: "l"(p), "f"(mx), "f"(my), "f"(mz), "f"(mw) : "memory");
    }
}

// ---------------------------------------------------------------------------
// Node linear: h = X @ W_node + b_node   (X: [N,64], W: [64,128])
// Writes g_H, g_H0 and g_AGG (agg seeded with h so atomics produce h + sum).
// Block = (32,8): thread (tx,ty) computes rows row0+ty*4..+3, cols tx*4..+3.
// ---------------------------------------------------------------------------
__global__ void __launch_bounds__(256) node_linear_kernel(
    const float* __restrict__ X,
    const float* __restrict__ W,
    const float* __restrict__ B)
{
    __shared__ float As[32][IN_NODE];   // 8 KB
    __shared__ float Ws[32][HID];       // 16 KB
    const int tx = threadIdx.x, ty = threadIdx.y;
    const int tid = ty * 32 + tx;
    const int row0 = blockIdx.x * 32;

    const float4* X4 = (const float4*)X;
    for (int i = tid; i < 32 * 16; i += 256) {
        int r = i >> 4, c = i & 15;
        ((float4*)&As[r][0])[c] = X4[(size_t)(row0 + r) * 16 + c];
    }

    float4 acc[4];
#pragma unroll
    for (int r = 0; r < 4; r++) acc[r] = make_float4(0.f, 0.f, 0.f, 0.f);

    const float4* W4 = (const float4*)W;
    for (int kk = 0; kk < IN_NODE; kk += 32) {
        __syncthreads();
        for (int i = tid; i < 32 * 32; i += 256) {
            int r = i >> 5, c = i & 31;
            ((float4*)&Ws[r][0])[c] = W4[(size_t)(kk + r) * 32 + c];
        }
        __syncthreads();
#pragma unroll
        for (int k = 0; k < 32; k += 4) {
            float4 w0 = *(const float4*)&Ws[k + 0][tx * 4];
            float4 w1 = *(const float4*)&Ws[k + 1][tx * 4];
            float4 w2 = *(const float4*)&Ws[k + 2][tx * 4];
            float4 w3 = *(const float4*)&Ws[k + 3][tx * 4];
#pragma unroll
            for (int r = 0; r < 4; r++) {
                float4 a = *(const float4*)&As[ty * 4 + r][kk + k];
                acc[r].x = fmaf(a.x, w0.x, acc[r].x);
                acc[r].y = fmaf(a.x, w0.y, acc[r].y);
                acc[r].z = fmaf(a.x, w0.z, acc[r].z);
                acc[r].w = fmaf(a.x, w0.w, acc[r].w);
                acc[r].x = fmaf(a.y, w1.x, acc[r].x);
                acc[r].y = fmaf(a.y, w1.y, acc[r].y);
                acc[r].z = fmaf(a.y, w1.z, acc[r].z);
                acc[r].w = fmaf(a.y, w1.w, acc[r].w);
                acc[r].x = fmaf(a.z, w2.x, acc[r].x);
                acc[r].y = fmaf(a.z, w2.y, acc[r].y);
                acc[r].z = fmaf(a.z, w2.z, acc[r].z);
                acc[r].w = fmaf(a.z, w2.w, acc[r].w);
                acc[r].x = fmaf(a.w, w3.x, acc[r].x);
                acc[r].y = fmaf(a.w, w3.y, acc[r].y);
                acc[r].z = fmaf(a.w, w3.z, acc[r].z);
                acc[r].w = fmaf(a.w, w3.w, acc[r].w);
            }
        }
    }

    float4 b4 = ((const float4*)B)[tx];
#pragma unroll
    for (int r = 0; r < 4; r++) {
        int grow = row0 + ty * 4 + r;
        float4 o = make_float4(acc[r].x + b4.x, acc[r].y + b4.y,
                               acc[r].z + b4.z, acc[r].w + b4.w);
        size_t off = (size_t)grow * 32 + tx;
        g_H[off]   = o;
        g_H0[off]  = o;
        g_AGG[off] = o;
    }
}

// ---------------------------------------------------------------------------
// Conv GEMM: H = leaky_relu(AGG @ W + b); also re-seed AGG := H for next layer.
// ---------------------------------------------------------------------------
__global__ void __launch_bounds__(256) conv_kernel(
    const float* __restrict__ W,
    const float* __restrict__ B)
{
    __shared__ float As[32][HID];   // 16 KB
    __shared__ float Ws[32][HID];   // 16 KB
    const int tx = threadIdx.x, ty = threadIdx.y;
    const int tid = ty * 32 + tx;
    const int row0 = blockIdx.x * 32;

    for (int i = tid; i < 32 * 32; i += 256) {
        int r = i >> 5, c = i & 31;
        ((float4*)&As[r][0])[c] = g_AGG[(size_t)(row0 + r) * 32 + c];
    }

    float4 acc[4];
#pragma unroll
    for (int r = 0; r < 4; r++) acc[r] = make_float4(0.f, 0.f, 0.f, 0.f);

    const float4* W4 = (const float4*)W;
    for (int kk = 0; kk < HID; kk += 32) {
        __syncthreads();
        for (int i = tid; i < 32 * 32; i += 256) {
            int r = i >> 5, c = i & 31;
            ((float4*)&Ws[r][0])[c] = W4[(size_t)(kk + r) * 32 + c];
        }
        __syncthreads();
#pragma unroll
        for (int k = 0; k < 32; k += 4) {
            float4 w0 = *(const float4*)&Ws[k + 0][tx * 4];
            float4 w1 = *(const float4*)&Ws[k + 1][tx * 4];
            float4 w2 = *(const float4*)&Ws[k + 2][tx * 4];
            float4 w3 = *(const float4*)&Ws[k + 3][tx * 4];
#pragma unroll
            for (int r = 0; r < 4; r++) {
                float4 a = *(const float4*)&As[ty * 4 + r][kk + k];
                acc[r].x = fmaf(a.x, w0.x, acc[r].x);
                acc[r].y = fmaf(a.x, w0.y, acc[r].y);
                acc[r].z = fmaf(a.x, w0.z, acc[r].z);
                acc[r].w = fmaf(a.x, w0.w, acc[r].w);
                acc[r].x = fmaf(a.y, w1.x, acc[r].x);
                acc[r].y = fmaf(a.y, w1.y, acc[r].y);
                acc[r].z = fmaf(a.y, w1.z, acc[r].z);
                acc[r].w = fmaf(a.y, w1.w, acc[r].w);
                acc[r].x = fmaf(a.z, w2.x, acc[r].x);
                acc[r].y = fmaf(a.z, w2.y, acc[r].y);
                acc[r].z = fmaf(a.z, w2.z, acc[r].z);
                acc[r].w = fmaf(a.z, w2.w, acc[r].w);
                acc[r].x = fmaf(a.w, w3.x, acc[r].x);
                acc[r].y = fmaf(a.w, w3.y, acc[r].y);
                acc[r].z = fmaf(a.w, w3.z, acc[r].z);
                acc[r].w = fmaf(a.w, w3.w, acc[r].w);
            }
        }
    }

    float4 b4 = ((const float4*)B)[tx];
#pragma unroll
    for (int r = 0; r < 4; r++) {
        int grow = row0 + ty * 4 + r;
        float ox = acc[r].x + b4.x;
        float oy = acc[r].y + b4.y;
        float oz = acc[r].z + b4.z;
        float ow = acc[r].w + b4.w;
        ox = (ox >= 0.f) ? ox : NEG_SLOPE * ox;
        oy = (oy >= 0.f) ? oy : NEG_SLOPE * oy;
        oz = (oz >= 0.f) ? oz : NEG_SLOPE * oz;
        ow = (ow >= 0.f) ? ow : NEG_SLOPE * ow;
        float4 o = make_float4(ox, oy, oz, ow);
        size_t off = (size_t)grow * 32 + tx;
        g_H[off]   = o;
        g_AGG[off] = o;   // seed next layer's aggregation with h
    }
}

// ---------------------------------------------------------------------------
// Head: y = (H0 + H) @ W_head + b; out = LayerNorm(y)*gamma + beta
// Each warp (fixed ty) owns 4 full rows -> LN via warp allreduce.
// ---------------------------------------------------------------------------
__global__ void __launch_bounds__(256) head_kernel(
    const float* __restrict__ W,
    const float* __restrict__ B,
    const float* __restrict__ G,
    const float* __restrict__ BT,
    float* __restrict__ OUT)
{
    __shared__ float As[32][HID];
    __shared__ float Ws[32][HID];
    const int tx = threadIdx.x, ty = threadIdx.y;
    const int tid = ty * 32 + tx;
    const int row0 = blockIdx.x * 32;

    for (int i = tid; i < 32 * 32; i += 256) {
        int r = i >> 5, c = i & 31;
        size_t off = (size_t)(row0 + r) * 32 + c;
        float4 a = g_H0[off];
        float4 b = g_H[off];
        ((float4*)&As[r][0])[c] =
            make_float4(a.x + b.x, a.y + b.y, a.z + b.z, a.w + b.w);
    }

    float4 acc[4];
#pragma unroll
    for (int r = 0; r < 4; r++) acc[r] = make_float4(0.f, 0.f, 0.f, 0.f);

    const float4* W4 = (const float4*)W;
    for (int kk = 0; kk < HID; kk += 32) {
        __syncthreads();
        for (int i = tid; i < 32 * 32; i += 256) {
            int r = i >> 5, c = i & 31;
            ((float4*)&Ws[r][0])[c] = W4[(size_t)(kk + r) * 32 + c];
        }
        __syncthreads();
#pragma unroll
        for (int k = 0; k < 32; k += 4) {
            float4 w0 = *(const float4*)&Ws[k + 0][tx * 4];
            float4 w1 = *(const float4*)&Ws[k + 1][tx * 4];
            float4 w2 = *(const float4*)&Ws[k + 2][tx * 4];
            float4 w3 = *(const float4*)&Ws[k + 3][tx * 4];
#pragma unroll
            for (int r = 0; r < 4; r++) {
                float4 a = *(const float4*)&As[ty * 4 + r][kk + k];
                acc[r].x = fmaf(a.x, w0.x, acc[r].x);
                acc[r].y = fmaf(a.x, w0.y, acc[r].y);
                acc[r].z = fmaf(a.x, w0.z, acc[r].z);
                acc[r].w = fmaf(a.x, w0.w, acc[r].w);
                acc[r].x = fmaf(a.y, w1.x, acc[r].x);
                acc[r].y = fmaf(a.y, w1.y, acc[r].y);
                acc[r].z = fmaf(a.y, w1.z, acc[r].z);
                acc[r].w = fmaf(a.y, w1.w, acc[r].w);
                acc[r].x = fmaf(a.z, w2.x, acc[r].x);
                acc[r].y = fmaf(a.z, w2.y, acc[r].y);
                acc[r].z = fmaf(a.z, w2.z, acc[r].z);
                acc[r].w = fmaf(a.z, w2.w, acc[r].w);
                acc[r].x = fmaf(a.w, w3.x, acc[r].x);
                acc[r].y = fmaf(a.w, w3.y, acc[r].y);
                acc[r].z = fmaf(a.w, w3.z, acc[r].z);
                acc[r].w = fmaf(a.w, w3.w, acc[r].w);
            }
        }
    }

    float4 b4 = ((const float4*)B)[tx];
    float4 g4 = ((const float4*)G)[tx];
    float4 t4 = ((const float4*)BT)[tx];
    float4* OUT4 = (float4*)OUT;

#pragma unroll
    for (int r = 0; r < 4; r++) {
        int grow = row0 + ty * 4 + r;
        float yx = acc[r].x + b4.x;
        float yy = acc[r].y + b4.y;
        float yz = acc[r].z + b4.z;
        float yw = acc[r].w + b4.w;
        float s = yx + yy + yz + yw;
#pragma unroll
        for (int off = 16; off > 0; off >>= 1)
            s += __shfl_xor_sync(0xffffffffu, s, off);
        float mu = s * (1.0f / HID);
        float dx = yx - mu, dy = yy - mu, dz = yz - mu, dw = yw - mu;
        float q = dx * dx + dy * dy + dz * dz + dw * dw;
#pragma unroll
        for (int off = 16; off > 0; off >>= 1)
            q += __shfl_xor_sync(0xffffffffu, q, off);
        float inv = rsqrtf(q * (1.0f / HID) + LN_EPS);
        float4 o = make_float4(dx * inv * g4.x + t4.x,
                               dy * inv * g4.y + t4.y,
                               dz * inv * g4.z + t4.z,
                               dw * inv * g4.w + t4.w);
        OUT4[(size_t)grow * 32 + tx] = o;
    }
}

// ---------------------------------------------------------------------------
extern "C" void kernel_launch(void* const* d_in, const int* in_sizes, int n_in,
                              void* d_out, int out_size)
{
    const float* x   = (const float*)d_in[0];
    const float* ea  = (const float*)d_in[1];
    const int*   ei  = (const int*)d_in[2];     // dtype resolved on device
    const float* Wn  = (const float*)d_in[3];
    const float* bn  = (const float*)d_in[4];
    const float* We  = (const float*)d_in[5];
    const float* be  = (const float*)d_in[6];
    const float* Wc  = (const float*)d_in[7];
    const float* bc  = (const float*)d_in[8];
    const float* Wh  = (const float*)d_in[9];
    const float* bh  = (const float*)d_in[10];
    const float* gam = (const float*)d_in[11];
    const float* bet = (const float*)d_in[12];
    float* out = (float*)d_out;

    dim3 blk(32, 8);
    const int gemm_grid = N_NODES / 32;   // 3125 (exact)
    // message: 2 edges per warp, 8 warps per block
    const int msg_grid = (N_EDGES / 2 + 7) / 8;   // 100000 blocks

    detect_kernel<<<1, 256>>>(ei);
    convert_kernel<<<(2 * N_EDGES + 255) / 256, 256>>>(ei);

    edge_linear_kernel<<<2048, 256>>>(ea, We, be);
    node_linear_kernel<<<gemm_grid, blk>>>(x, Wn, bn);
    for (int l = 0; l < 3; l++) {
        message_kernel<<<msg_grid, 256>>>();
        conv_kernel<<<gemm_grid, blk>>>(Wc + (size_t)l * HID * HID, bc + l * HID);
    }
    head_kernel<<<gemm_grid, blk>>>(Wh, bh, gam, bet, out);
}

// round 9
// speedup vs baseline: 2.0853x; 1.2762x over previous
#include <cuda_runtime.h>
#include <cuda_fp16.h>
#include <cuda_bf16.h>
#include <cstdint>

#define N_NODES 100000
#define N_EDGES 1600000
#define HID     128
#define IN_NODE 64
#define IN_EDGE 16
#define NEG_SLOPE 0.01f
#define LN_EPS    1e-5f

// Persistent scratch (no allocations allowed).
__device__ float4 g_H  [(size_t)N_NODES * (HID / 4)];   // 51.2 MB (L2-resident)
__device__ float4 g_H0 [(size_t)N_NODES * (HID / 4)];   // 51.2 MB
__device__ float4 g_AGG[(size_t)N_NODES * (HID / 4)];   // 51.2 MB (L2-resident)
// E = edge_attr @ W_edge + b_edge, fp16: per edge 128 halves; lane holds 4 (uint2).
__device__ uint2  g_E2 [(size_t)N_EDGES * 32];          // 409.6 MB, streamed (.cs)

// Edge indices normalized to int32 regardless of input dtype.
__device__ int g_src[N_EDGES];
__device__ int g_dst[N_EDGES];
__device__ int g_is32;   // 1 if edge_index buffer is int32, 0 if int64

// ---------------------------------------------------------------------------
// Detect edge_index dtype by sampling odd 32-bit words.
// int64 (nonneg, < 2^31): odd words are high-words == 0 -> OR == 0.
// int32: odd words are random indices in [0, N_NODES) -> OR != 0 (w.p. ~1).
// ---------------------------------------------------------------------------
__global__ void detect_kernel(const int* __restrict__ ei32)
{
    __shared__ int s_or;
    if (threadIdx.x == 0) s_or = 0;
    __syncthreads();
    int v = 0;
    for (int i = threadIdx.x; i < 4096; i += blockDim.x)
        v |= ei32[2 * i + 1];
    atomicOr(&s_or, v);
    __syncthreads();
    if (threadIdx.x == 0) g_is32 = (s_or != 0) ? 1 : 0;
}

// Normalize edge_index into g_src / g_dst (int32).
__global__ void convert_kernel(const int* __restrict__ ei32)
{
    int i = blockIdx.x * blockDim.x + threadIdx.x;
    if (i >= 2 * N_EDGES) return;
    int v = g_is32 ? ei32[i] : ei32[2 * i];
    if (i < N_EDGES) g_src[i] = v;
    else             g_dst[i - N_EDGES] = v;
}

// ---------------------------------------------------------------------------
// Edge linear (once): g_E2[e] = fp16(edge_attr[e] @ W_edge + b_edge).
// One warp per edge (grid-stride); lane owns cols lane*4..+3.
// Streaming loads/stores (.cs) keep L2 free for H/AGG.
// ---------------------------------------------------------------------------
__global__ void __launch_bounds__(256) edge_linear_kernel(
    const float* __restrict__ EA,
    const float* __restrict__ WE,
    const float* __restrict__ BE)
{
    const int lane = threadIdx.x & 31;
    const int warp  = (blockIdx.x * blockDim.x + threadIdx.x) >> 5;
    const int nwarp = (gridDim.x * blockDim.x) >> 5;

    const float4* WE4 = (const float4*)WE;
    float4 wreg[16];
#pragma unroll
    for (int k = 0; k < 16; k++) wreg[k] = WE4[k * 32 + lane];
    const float4 be = ((const float4*)BE)[lane];

    const float4* EA4 = (const float4*)EA;

    for (int e = warp; e < N_EDGES; e += nwarp) {
        float4 ea0 = __ldcs(&EA4[(size_t)e * 4 + 0]);
        float4 ea1 = __ldcs(&EA4[(size_t)e * 4 + 1]);
        float4 ea2 = __ldcs(&EA4[(size_t)e * 4 + 2]);
        float4 ea3 = __ldcs(&EA4[(size_t)e * 4 + 3]);
        float ev[16] = { ea0.x, ea0.y, ea0.z, ea0.w,
                         ea1.x, ea1.y, ea1.z, ea1.w,
                         ea2.x, ea2.y, ea2.z, ea2.w,
                         ea3.x, ea3.y, ea3.z, ea3.w };
        float4 acc = be;
#pragma unroll
        for (int k = 0; k < 16; k++) {
            acc.x = fmaf(ev[k], wreg[k].x, acc.x);
            acc.y = fmaf(ev[k], wreg[k].y, acc.y);
            acc.z = fmaf(ev[k], wreg[k].z, acc.z);
            acc.w = fmaf(ev[k], wreg[k].w, acc.w);
        }
        uint2 pk;
        ((__half2*)&pk)[0] = __floats2half2_rn(acc.x, acc.y);
        ((__half2*)&pk)[1] = __floats2half2_rn(acc.z, acc.w);
        __stcs(&g_E2[(size_t)e * 32 + lane], pk);
    }
}

// ---------------------------------------------------------------------------
// Message kernel (per layer): AGG[d] += relu(h[s] + e) via red.global.add.v4.
// 4 edges per warp, front-batched loads for MLP; E read with .cs (no L2 pollution).
// ---------------------------------------------------------------------------
__global__ void __launch_bounds__(256) message_kernel()
{
    const int lane = threadIdx.x & 31;
    const int warp = (blockIdx.x * blockDim.x + threadIdx.x) >> 5;
    const int e0 = warp * 4;   // N_EDGES divisible by 4; grid sized exactly

    int s[4], d[4];
#pragma unroll
    for (int i = 0; i < 4; i++) { s[i] = g_src[e0 + i]; d[i] = g_dst[e0 + i]; }

    uint2 ep[4];
#pragma unroll
    for (int i = 0; i < 4; i++)
        ep[i] = __ldcs(&g_E2[(size_t)(e0 + i) * 32 + lane]);

    float4 hv[4];
#pragma unroll
    for (int i = 0; i < 4; i++) {
        bool ok = (unsigned)s[i] < N_NODES;
        hv[i] = ok ? g_H[(size_t)s[i] * 32 + lane] : make_float4(0, 0, 0, 0);
    }

#pragma unroll
    for (int i = 0; i < 4; i++) {
        if ((unsigned)s[i] >= N_NODES || (unsigned)d[i] >= N_NODES) continue;
        float2 elo = __half22float2(((const __half2*)&ep[i])[0]);
        float2 ehi = __half22float2(((const __half2*)&ep[i])[1]);
        float mx = fmaxf(hv[i].x + elo.x, 0.f);
        float my = fmaxf(hv[i].y + elo.y, 0.f);
        float mz = fmaxf(hv[i].z + ehi.x, 0.f);
        float mw = fmaxf(hv[i].w + ehi.y, 0.f);
        float4* p = &g_AGG[(size_t)d[i] * 32 + lane];
        asm volatile("red.global.add.v4.f32 [%0], {%1,%2,%3,%4};"
                     :: "l"(p), "f"(mx), "f"(my), "f"(mz), "f"(mw) : "memory");
    }
}

// ---------------------------------------------------------------------------
// Node linear: h = X @ W_node + b_node   (X: [N,64], W: [64,128])
// Writes g_H, g_H0 and g_AGG (agg seeded with h so atomics produce h + sum).
// ---------------------------------------------------------------------------
__global__ void __launch_bounds__(256) node_linear_kernel(
    const float* __restrict__ X,
    const float* __restrict__ W,
    const float* __restrict__ B)
{
    __shared__ float As[32][IN_NODE];
    __shared__ float Ws[32][HID];
    const int tx = threadIdx.x, ty = threadIdx.y;
    const int tid = ty * 32 + tx;
    const int row0 = blockIdx.x * 32;

    const float4* X4 = (const float4*)X;
    for (int i = tid; i < 32 * 16; i += 256) {
        int r = i >> 4, c = i & 15;
        ((float4*)&As[r][0])[c] = X4[(size_t)(row0 + r) * 16 + c];
    }

    float4 acc[4];
#pragma unroll
    for (int r = 0; r < 4; r++) acc[r] = make_float4(0.f, 0.f, 0.f, 0.f);

    const float4* W4 = (const float4*)W;
    for (int kk = 0; kk < IN_NODE; kk += 32) {
        __syncthreads();
        for (int i = tid; i < 32 * 32; i += 256) {
            int r = i >> 5, c = i & 31;
            ((float4*)&Ws[r][0])[c] = W4[(size_t)(kk + r) * 32 + c];
        }
        __syncthreads();
#pragma unroll
        for (int k = 0; k < 32; k += 4) {
            float4 w0 = *(const float4*)&Ws[k + 0][tx * 4];
            float4 w1 = *(const float4*)&Ws[k + 1][tx * 4];
            float4 w2 = *(const float4*)&Ws[k + 2][tx * 4];
            float4 w3 = *(const float4*)&Ws[k + 3][tx * 4];
#pragma unroll
            for (int r = 0; r < 4; r++) {
                float4 a = *(const float4*)&As[ty * 4 + r][kk + k];
                acc[r].x = fmaf(a.x, w0.x, acc[r].x);
                acc[r].y = fmaf(a.x, w0.y, acc[r].y);
                acc[r].z = fmaf(a.x, w0.z, acc[r].z);
                acc[r].w = fmaf(a.x, w0.w, acc[r].w);
                acc[r].x = fmaf(a.y, w1.x, acc[r].x);
                acc[r].y = fmaf(a.y, w1.y, acc[r].y);
                acc[r].z = fmaf(a.y, w1.z, acc[r].z);
                acc[r].w = fmaf(a.y, w1.w, acc[r].w);
                acc[r].x = fmaf(a.z, w2.x, acc[r].x);
                acc[r].y = fmaf(a.z, w2.y, acc[r].y);
                acc[r].z = fmaf(a.z, w2.z, acc[r].z);
                acc[r].w = fmaf(a.z, w2.w, acc[r].w);
                acc[r].x = fmaf(a.w, w3.x, acc[r].x);
                acc[r].y = fmaf(a.w, w3.y, acc[r].y);
                acc[r].z = fmaf(a.w, w3.z, acc[r].z);
                acc[r].w = fmaf(a.w, w3.w, acc[r].w);
            }
        }
    }

    float4 b4 = ((const float4*)B)[tx];
#pragma unroll
    for (int r = 0; r < 4; r++) {
        int grow = row0 + ty * 4 + r;
        float4 o = make_float4(acc[r].x + b4.x, acc[r].y + b4.y,
                               acc[r].z + b4.z, acc[r].w + b4.w);
        size_t off = (size_t)grow * 32 + tx;
        g_H[off]   = o;
        g_H0[off]  = o;
        g_AGG[off] = o;
    }
}

// ---------------------------------------------------------------------------
// Conv GEMM: H = leaky_relu(AGG @ W + b); also re-seed AGG := H for next layer.
// ---------------------------------------------------------------------------
__global__ void __launch_bounds__(256) conv_kernel(
    const float* __restrict__ W,
    const float* __restrict__ B)
{
    __shared__ float As[32][HID];
    __shared__ float Ws[32][HID];
    const int tx = threadIdx.x, ty = threadIdx.y;
    const int tid = ty * 32 + tx;
    const int row0 = blockIdx.x * 32;

    for (int i = tid; i < 32 * 32; i += 256) {
        int r = i >> 5, c = i & 31;
        ((float4*)&As[r][0])[c] = g_AGG[(size_t)(row0 + r) * 32 + c];
    }

    float4 acc[4];
#pragma unroll
    for (int r = 0; r < 4; r++) acc[r] = make_float4(0.f, 0.f, 0.f, 0.f);

    const float4* W4 = (const float4*)W;
    for (int kk = 0; kk < HID; kk += 32) {
        __syncthreads();
        for (int i = tid; i < 32 * 32; i += 256) {
            int r = i >> 5, c = i & 31;
            ((float4*)&Ws[r][0])[c] = W4[(size_t)(kk + r) * 32 + c];
        }
        __syncthreads();
#pragma unroll
        for (int k = 0; k < 32; k += 4) {
            float4 w0 = *(const float4*)&Ws[k + 0][tx * 4];
            float4 w1 = *(const float4*)&Ws[k + 1][tx * 4];
            float4 w2 = *(const float4*)&Ws[k + 2][tx * 4];
            float4 w3 = *(const float4*)&Ws[k + 3][tx * 4];
#pragma unroll
            for (int r = 0; r < 4; r++) {
                float4 a = *(const float4*)&As[ty * 4 + r][kk + k];
                acc[r].x = fmaf(a.x, w0.x, acc[r].x);
                acc[r].y = fmaf(a.x, w0.y, acc[r].y);
                acc[r].z = fmaf(a.x, w0.z, acc[r].z);
                acc[r].w = fmaf(a.x, w0.w, acc[r].w);
                acc[r].x = fmaf(a.y, w1.x, acc[r].x);
                acc[r].y = fmaf(a.y, w1.y, acc[r].y);
                acc[r].z = fmaf(a.y, w1.z, acc[r].z);
                acc[r].w = fmaf(a.y, w1.w, acc[r].w);
                acc[r].x = fmaf(a.z, w2.x, acc[r].x);
                acc[r].y = fmaf(a.z, w2.y, acc[r].y);
                acc[r].z = fmaf(a.z, w2.z, acc[r].z);
                acc[r].w = fmaf(a.z, w2.w, acc[r].w);
                acc[r].x = fmaf(a.w, w3.x, acc[r].x);
                acc[r].y = fmaf(a.w, w3.y, acc[r].y);
                acc[r].z = fmaf(a.w, w3.z, acc[r].z);
                acc[r].w = fmaf(a.w, w3.w, acc[r].w);
            }
        }
    }

    float4 b4 = ((const float4*)B)[tx];
#pragma unroll
    for (int r = 0; r < 4; r++) {
        int grow = row0 + ty * 4 + r;
        float ox = acc[r].x + b4.x;
        float oy = acc[r].y + b4.y;
        float oz = acc[r].z + b4.z;
        float ow = acc[r].w + b4.w;
        ox = (ox >= 0.f) ? ox : NEG_SLOPE * ox;
        oy = (oy >= 0.f) ? oy : NEG_SLOPE * oy;
        oz = (oz >= 0.f) ? oz : NEG_SLOPE * oz;
        ow = (ow >= 0.f) ? ow : NEG_SLOPE * ow;
        float4 o = make_float4(ox, oy, oz, ow);
        size_t off = (size_t)grow * 32 + tx;
        g_H[off]   = o;
        g_AGG[off] = o;
    }
}

// ---------------------------------------------------------------------------
// Head: y = (H0 + H) @ W_head + b; out = LayerNorm(y)*gamma + beta
// ---------------------------------------------------------------------------
__global__ void __launch_bounds__(256) head_kernel(
    const float* __restrict__ W,
    const float* __restrict__ B,
    const float* __restrict__ G,
    const float* __restrict__ BT,
    float* __restrict__ OUT)
{
    __shared__ float As[32][HID];
    __shared__ float Ws[32][HID];
    const int tx = threadIdx.x, ty = threadIdx.y;
    const int tid = ty * 32 + tx;
    const int row0 = blockIdx.x * 32;

    for (int i = tid; i < 32 * 32; i += 256) {
        int r = i >> 5, c = i & 31;
        size_t off = (size_t)(row0 + r) * 32 + c;
        float4 a = g_H0[off];
        float4 b = g_H[off];
        ((float4*)&As[r][0])[c] =
            make_float4(a.x + b.x, a.y + b.y, a.z + b.z, a.w + b.w);
    }

    float4 acc[4];
#pragma unroll
    for (int r = 0; r < 4; r++) acc[r] = make_float4(0.f, 0.f, 0.f, 0.f);

    const float4* W4 = (const float4*)W;
    for (int kk = 0; kk < HID; kk += 32) {
        __syncthreads();
        for (int i = tid; i < 32 * 32; i += 256) {
            int r = i >> 5, c = i & 31;
            ((float4*)&Ws[r][0])[c] = W4[(size_t)(kk + r) * 32 + c];
        }
        __syncthreads();
#pragma unroll
        for (int k = 0; k < 32; k += 4) {
            float4 w0 = *(const float4*)&Ws[k + 0][tx * 4];
            float4 w1 = *(const float4*)&Ws[k + 1][tx * 4];
            float4 w2 = *(const float4*)&Ws[k + 2][tx * 4];
            float4 w3 = *(const float4*)&Ws[k + 3][tx * 4];
#pragma unroll
            for (int r = 0; r < 4; r++) {
                float4 a = *(const float4*)&As[ty * 4 + r][kk + k];
                acc[r].x = fmaf(a.x, w0.x, acc[r].x);
                acc[r].y = fmaf(a.x, w0.y, acc[r].y);
                acc[r].z = fmaf(a.x, w0.z, acc[r].z);
                acc[r].w = fmaf(a.x, w0.w, acc[r].w);
                acc[r].x = fmaf(a.y, w1.x, acc[r].x);
                acc[r].y = fmaf(a.y, w1.y, acc[r].y);
                acc[r].z = fmaf(a.y, w1.z, acc[r].z);
                acc[r].w = fmaf(a.y, w1.w, acc[r].w);
                acc[r].x = fmaf(a.z, w2.x, acc[r].x);
                acc[r].y = fmaf(a.z, w2.y, acc[r].y);
                acc[r].z = fmaf(a.z, w2.z, acc[r].z);
                acc[r].w = fmaf(a.z, w2.w, acc[r].w);
                acc[r].x = fmaf(a.w, w3.x, acc[r].x);
                acc[r].y = fmaf(a.w, w3.y, acc[r].y);
                acc[r].z = fmaf(a.w, w3.z, acc[r].z);
                acc[r].w = fmaf(a.w, w3.w, acc[r].w);
            }
        }
    }

    float4 b4 = ((const float4*)B)[tx];
    float4 g4 = ((const float4*)G)[tx];
    float4 t4 = ((const float4*)BT)[tx];
    float4* OUT4 = (float4*)OUT;

#pragma unroll
    for (int r = 0; r < 4; r++) {
        int grow = row0 + ty * 4 + r;
        float yx = acc[r].x + b4.x;
        float yy = acc[r].y + b4.y;
        float yz = acc[r].z + b4.z;
        float yw = acc[r].w + b4.w;
        float s = yx + yy + yz + yw;
#pragma unroll
        for (int off = 16; off > 0; off >>= 1)
            s += __shfl_xor_sync(0xffffffffu, s, off);
        float mu = s * (1.0f / HID);
        float dx = yx - mu, dy = yy - mu, dz = yz - mu, dw = yw - mu;
        float q = dx * dx + dy * dy + dz * dz + dw * dw;
#pragma unroll
        for (int off = 16; off > 0; off >>= 1)
            q += __shfl_xor_sync(0xffffffffu, q, off);
        float inv = rsqrtf(q * (1.0f / HID) + LN_EPS);
        float4 o = make_float4(dx * inv * g4.x + t4.x,
                               dy * inv * g4.y + t4.y,
                               dz * inv * g4.z + t4.z,
                               dw * inv * g4.w + t4.w);
        OUT4[(size_t)grow * 32 + tx] = o;
    }
}

// ---------------------------------------------------------------------------
extern "C" void kernel_launch(void* const* d_in, const int* in_sizes, int n_in,
                              void* d_out, int out_size)
{
    const float* x   = (const float*)d_in[0];
    const float* ea  = (const float*)d_in[1];
    const int*   ei  = (const int*)d_in[2];
    const float* Wn  = (const float*)d_in[3];
    const float* bn  = (const float*)d_in[4];
    const float* We  = (const float*)d_in[5];
    const float* be  = (const float*)d_in[6];
    const float* Wc  = (const float*)d_in[7];
    const float* bc  = (const float*)d_in[8];
    const float* Wh  = (const float*)d_in[9];
    const float* bh  = (const float*)d_in[10];
    const float* gam = (const float*)d_in[11];
    const float* bet = (const float*)d_in[12];
    float* out = (float*)d_out;

    dim3 blk(32, 8);
    const int gemm_grid = N_NODES / 32;          // 3125 (exact)
    const int msg_grid  = N_EDGES / (4 * 8);     // 50000 blocks (exact)

    detect_kernel<<<1, 256>>>(ei);
    convert_kernel<<<(2 * N_EDGES + 255) / 256, 256>>>(ei);

    edge_linear_kernel<<<2048, 256>>>(ea, We, be);
    node_linear_kernel<<<gemm_grid, blk>>>(x, Wn, bn);
    for (int l = 0; l < 3; l++) {
        message_kernel<<<msg_grid, 256>>>();
        conv_kernel<<<gemm_grid, blk>>>(Wc + (size_t)l * HID * HID, bc + l * HID);
    }
    head_kernel<<<gemm_grid, blk>>>(Wh, bh, gam, bet, out);
}